// round 1
// baseline (speedup 1.0000x reference)
#include <cuda_runtime.h>

#define B_ 16
#define T_ 1024
#define D_ 1024
#define M_ (B_ * T_)            // 16384
#define NELEM (B_ * T_ * D_)    // 16777216

// Scratch (static device globals; no dynamic allocation allowed)
__device__ float g_xt[NELEM];   // tanh(0.5*x)
__device__ float g_ic[NELEM];   // tanh(xt @ W^T)

// ---------------------------------------------------------------------------
// Kernel 1: xt = tanh(0.5 * x), vectorized float4
// ---------------------------------------------------------------------------
__global__ void tanh_half_kernel(const float* __restrict__ x) {
    int i = blockIdx.x * blockDim.x + threadIdx.x;   // over NELEM/4
    float4 v = ((const float4*)x)[i];
    float4 o;
    o.x = tanhf(0.5f * v.x);
    o.y = tanhf(0.5f * v.y);
    o.z = tanhf(0.5f * v.z);
    o.w = tanhf(0.5f * v.w);
    ((float4*)g_xt)[i] = o;
}

// ---------------------------------------------------------------------------
// Kernel 2: ic[m,n] = tanh( sum_k xt[m,k] * W[n,k] )
// Classic 128x128 block tile, 8x8 per thread, BK=8, FP32 FMA (accuracy!).
// grid = (N/128, M/128) = (8, 128), block = 256 threads.
// ---------------------------------------------------------------------------
__global__ __launch_bounds__(256, 2)
void sgemm_tanh_kernel(const float* __restrict__ W) {
    __shared__ float As[8][128];
    __shared__ float Bs[8][128];

    const int tid = threadIdx.x;
    const int tx = tid & 15;          // 0..15 -> N
    const int ty = tid >> 4;          // 0..15 -> M
    const int loadRow = tid >> 1;     // 0..127
    const int loadK = (tid & 1) << 2; // 0 or 4

    const float* Aptr = g_xt + (size_t)(blockIdx.y * 128 + loadRow) * D_ + loadK;
    const float* Bptr = W    + (size_t)(blockIdx.x * 128 + loadRow) * D_ + loadK;

    float acc[8][8];
#pragma unroll
    for (int i = 0; i < 8; i++)
#pragma unroll
        for (int j = 0; j < 8; j++) acc[i][j] = 0.0f;

    for (int kt = 0; kt < D_; kt += 8) {
        float4 a4 = *(const float4*)(Aptr + kt);
        float4 b4 = *(const float4*)(Bptr + kt);
        __syncthreads();
        As[loadK + 0][loadRow] = a4.x;
        As[loadK + 1][loadRow] = a4.y;
        As[loadK + 2][loadRow] = a4.z;
        As[loadK + 3][loadRow] = a4.w;
        Bs[loadK + 0][loadRow] = b4.x;
        Bs[loadK + 1][loadRow] = b4.y;
        Bs[loadK + 2][loadRow] = b4.z;
        Bs[loadK + 3][loadRow] = b4.w;
        __syncthreads();
#pragma unroll
        for (int k = 0; k < 8; k++) {
            float a[8], b[8];
            *(float4*)(a + 0) = *(const float4*)&As[k][ty * 8 + 0];
            *(float4*)(a + 4) = *(const float4*)&As[k][ty * 8 + 4];
            *(float4*)(b + 0) = *(const float4*)&Bs[k][tx * 8 + 0];
            *(float4*)(b + 4) = *(const float4*)&Bs[k][tx * 8 + 4];
#pragma unroll
            for (int i = 0; i < 8; i++)
#pragma unroll
                for (int j = 0; j < 8; j++) acc[i][j] += a[i] * b[j];
        }
    }

    const int row0 = blockIdx.y * 128 + ty * 8;
    const int col0 = blockIdx.x * 128 + tx * 8;
#pragma unroll
    for (int i = 0; i < 8; i++) {
        float4 v0, v1;
        v0.x = tanhf(acc[i][0]);
        v0.y = tanhf(acc[i][1]);
        v0.z = tanhf(acc[i][2]);
        v0.w = tanhf(acc[i][3]);
        v1.x = tanhf(acc[i][4]);
        v1.y = tanhf(acc[i][5]);
        v1.z = tanhf(acc[i][6]);
        v1.w = tanhf(acc[i][7]);
        float* cp = g_ic + (size_t)(row0 + i) * D_ + col0;
        *(float4*)(cp + 0) = v0;
        *(float4*)(cp + 4) = v1;
    }
}

// ---------------------------------------------------------------------------
// Kernel 3: LIF scan over T per (b,d) chain + fused output blend.
// 16384 threads, one per chain. Unroll-8 with prefetched loads for MLP.
// ---------------------------------------------------------------------------
__global__ void lif_kernel(const float* __restrict__ noise,
                           const float* __restrict__ rs,
                           float* __restrict__ out) {
    const int j = blockIdx.x * blockDim.x + threadIdx.x;  // 0..16383
    const int b = j >> 10;
    const int d = j & 1023;
    const size_t base = (size_t)b * T_ * D_ + d;

    const float r = 1.0f / (1.0f + expf(-rs[0]));
    const float one_m_r = 1.0f - r;

    float mem = 0.0f;
    for (int t = 0; t < T_; t += 8) {
        float icv[8], nzv[8], xtv[8];
#pragma unroll
        for (int u = 0; u < 8; u++) {
            size_t idx = base + (size_t)(t + u) * D_;
            icv[u] = g_ic[idx];
            nzv[u] = noise[idx];
            xtv[u] = g_xt[idx];
        }
#pragma unroll
        for (int u = 0; u < 8; u++) {
            // mem = DECAY*mem + ic + noise*(NOISE_SCALE*THRESHOLD) + 1e-6
            mem = 0.95f * mem + icv[u] + nzv[u] * 7.5e-4f + 1e-6f;
            float s = (mem >= 0.15f) ? 1.0f : 0.0f;
            mem = (mem >= 0.15f) ? -0.05f : mem;  // reset: mem*(1-s) - 0.05*s
            float o = tanhf((r * (s * icv[u] * 0.5f) + one_m_r * xtv[u]) * 0.5f);
            out[base + (size_t)(t + u) * D_] = o;
        }
    }
}

// ---------------------------------------------------------------------------
extern "C" void kernel_launch(void* const* d_in, const int* in_sizes, int n_in,
                              void* d_out, int out_size) {
    (void)out_size;
    const float* x = nullptr;
    const float* W = nullptr;
    const float* rs = nullptr;
    const float* nz = nullptr;
    for (int i = 0; i < n_in; i++) {
        if (in_sizes[i] == NELEM) {
            if (!x) x = (const float*)d_in[i];      // first (B,T,D) tensor = x
            else nz = (const float*)d_in[i];        // second = noise
        } else if (in_sizes[i] == D_ * D_) {
            W = (const float*)d_in[i];
        } else if (in_sizes[i] == 1) {
            rs = (const float*)d_in[i];
        }
    }

    // 1) xt = tanh(0.5*x)
    tanh_half_kernel<<<(NELEM / 4) / 256, 256>>>(x);

    // 2) ic = tanh(xt @ W^T), FP32
    dim3 ggrid(D_ / 128, M_ / 128);  // (8, 128)
    sgemm_tanh_kernel<<<ggrid, 256>>>(W);

    // 3) LIF scan + output
    lif_kernel<<<M_ * D_ / (T_ * 128), 128>>>(nz, rs, (float*)d_out);
}